// round 15
// baseline (speedup 1.0000x reference)
#include <cuda_runtime.h>
#include <cuda_fp16.h>
#include <cstdint>

#define NN 100000
#define NE 3200000
#define NG 256
#define NBLK 391   // ceil(NN/256)

// ---- weight plane offsets (elements) ----
#define OFF_W1  0          // 128x128  = 16384
#define OFF_W2  16384      // 256x128  = 32768
#define OFF_W3  49152      // 512x256  = 131072
#define OFF_L1  180224     // 1024x512 = 524288
#define OFF_L2  704512     // 512x1024 = 524288  -> end 1228800

// ================= device scratch (no allocations allowed) =================
__device__ int   g_cnt[NN];
__device__ int   g_rowptr[NN + 1];
__device__ int   g_cursor[NN];
__device__ int   g_bsum[NBLK];
__device__ int2  g_edge[NE];                  // (src, wgt bits) packed
__device__ float g_is[NN];
__device__ __half g_Ahi[(size_t)NN * 256];
__device__ __half g_act1[(size_t)NN * 1024];
__device__ __half g_act2[(size_t)NN * 1024];
__device__ __half g_Whi[1 << 21];
__device__ float g_gsum[NG * 4];
__device__ int   g_gcnt[NG];

__device__ __forceinline__ uint32_t smem_u32(const void* p) {
    uint32_t a;
    asm("{ .reg .u64 t; cvta.to.shared.u64 t, %1; cvt.u32.u64 %0, t; }" : "=r"(a) : "l"(p));
    return a;
}

// ================= graph preprocessing =================
__global__ void zero_kernel() {
    int i = blockIdx.x * blockDim.x + threadIdx.x;
    if (i < NN) g_cnt[i] = 0;
    if (i < NG * 4) g_gsum[i] = 0.f;
    if (i < NG) g_gcnt[i] = 0;
}

__global__ void hist_kernel(const int* __restrict__ dst) {
    int e = blockIdx.x * blockDim.x + threadIdx.x;
    if (e < NE) atomicAdd(&g_cnt[dst[e]], 1);
}

__global__ void scan1_kernel() {
    int i = blockIdx.x * 256 + threadIdx.x;
    int v = (i < NN) ? g_cnt[i] : 0;
#pragma unroll
    for (int o = 16; o > 0; o >>= 1) v += __shfl_down_sync(0xffffffffu, v, o);
    __shared__ int ws[8];
    if ((threadIdx.x & 31) == 0) ws[threadIdx.x >> 5] = v;
    __syncthreads();
    if (threadIdx.x < 8) {
        int s = ws[threadIdx.x];
#pragma unroll
        for (int o = 4; o > 0; o >>= 1) s += __shfl_down_sync(0xffu, s, o);
        if (threadIdx.x == 0) g_bsum[blockIdx.x] = s;
    }
}

__global__ void scan2_kernel() {
    int tid = threadIdx.x;
    int v = (tid < NBLK) ? g_bsum[tid] : 0;
    __shared__ int sm[512];
    sm[tid] = v;
    __syncthreads();
    for (int o = 1; o < 512; o <<= 1) {
        int a = (tid >= o) ? sm[tid - o] : 0;
        __syncthreads();
        sm[tid] += a;
        __syncthreads();
    }
    if (tid < NBLK) g_bsum[tid] = sm[tid] - v;
    if (tid == NBLK - 1) g_rowptr[NN] = sm[tid];
}

// scan3 also folds invsqrt and the batch histogram (graph node counts)
__global__ void scan3_kernel(const int* __restrict__ batch) {
    int i = blockIdx.x * 256 + threadIdx.x;
    int v = (i < NN) ? g_cnt[i] : 0;
    int lane = threadIdx.x & 31, w = threadIdx.x >> 5;
    int x = v;
#pragma unroll
    for (int o = 1; o < 32; o <<= 1) {
        int t = __shfl_up_sync(0xffffffffu, x, o);
        if (lane >= o) x += t;
    }
    __shared__ int ws[8];
    if (lane == 31) ws[w] = x;
    __syncthreads();
    if (threadIdx.x < 8) {
        int s = ws[threadIdx.x];
#pragma unroll
        for (int o = 1; o < 8; o <<= 1) {
            int t = __shfl_up_sync(0xffu, s, o);
            if ((int)threadIdx.x >= o) s += t;
        }
        ws[threadIdx.x] = s;
    }
    __syncthreads();
    int excl = x - v + (w ? ws[w - 1] : 0) + g_bsum[blockIdx.x];
    if (i < NN) {
        g_rowptr[i] = excl;
        g_cursor[i] = excl;
        g_is[i] = rsqrtf((float)(v + 1));
        atomicAdd(&g_gcnt[batch[i]], 1);   // folded batch histogram
    }
}

__global__ void csr_fill_kernel(const int* __restrict__ src, const int* __restrict__ dst) {
    int e = blockIdx.x * blockDim.x + threadIdx.x;
    if (e >= NE) return;
    int d = dst[e];
    int s = src[e];
    int p = atomicAdd(&g_cursor[d], 1);
    g_edge[p] = make_int2(s, __float_as_int(g_is[s] * g_is[d]));
}

// ================= fp32 x -> fp16 plane =================
__global__ void xconv_kernel(const float* __restrict__ x, __half* __restrict__ o, size_t total) {
    size_t i = blockIdx.x * (size_t)blockDim.x + threadIdx.x;
    if (i < total) o[i] = __float2half_rn(x[i]);
}

// ================= aggregation: fp16 gather, fp32 accum, fp16 out ============
template <int H>
__global__ void agg16_kernel(const __half* __restrict__ h, __half* __restrict__ outHi) {
    const int node = blockIdx.x * 4 + (threadIdx.x >> 5);
    if (node >= NN) return;
    const int lane = threadIdx.x & 31;
    constexpr int U = H / 128;

    float acc[U][4];
    float self = g_is[node];
    self = self * self;
    const uint2* hrow = (const uint2*)(h + (size_t)node * H);
#pragma unroll
    for (int u = 0; u < U; u++) {
        uint2 t = hrow[lane + 32 * u];
        float2 a = __half22float2(*(const __half2*)&t.x);
        float2 b = __half22float2(*(const __half2*)&t.y);
        acc[u][0] = self * a.x; acc[u][1] = self * a.y;
        acc[u][2] = self * b.x; acc[u][3] = self * b.y;
    }
    const int beg = g_rowptr[node];
    const int end = g_rowptr[node + 1];
    int p = beg;
    for (; p + 2 <= end; p += 2) {
        int2 e0 = g_edge[p], e1 = g_edge[p + 1];
        float w0 = __int_as_float(e0.y), w1 = __int_as_float(e1.y);
        const uint2* s0 = (const uint2*)(h + (size_t)e0.x * H);
        const uint2* s1 = (const uint2*)(h + (size_t)e1.x * H);
#pragma unroll
        for (int u = 0; u < U; u++) {
            uint2 t0 = s0[lane + 32 * u];
            uint2 t1 = s1[lane + 32 * u];
            float2 a0 = __half22float2(*(const __half2*)&t0.x);
            float2 b0 = __half22float2(*(const __half2*)&t0.y);
            float2 a1 = __half22float2(*(const __half2*)&t1.x);
            float2 b1 = __half22float2(*(const __half2*)&t1.y);
            acc[u][0] += w0 * a0.x + w1 * a1.x;
            acc[u][1] += w0 * a0.y + w1 * a1.y;
            acc[u][2] += w0 * b0.x + w1 * b1.x;
            acc[u][3] += w0 * b0.y + w1 * b1.y;
        }
    }
    if (p < end) {
        int2 e0 = g_edge[p];
        float w0 = __int_as_float(e0.y);
        const uint2* s0 = (const uint2*)(h + (size_t)e0.x * H);
#pragma unroll
        for (int u = 0; u < U; u++) {
            uint2 t0 = s0[lane + 32 * u];
            float2 a0 = __half22float2(*(const __half2*)&t0.x);
            float2 b0 = __half22float2(*(const __half2*)&t0.y);
            acc[u][0] += w0 * a0.x; acc[u][1] += w0 * a0.y;
            acc[u][2] += w0 * b0.x; acc[u][3] += w0 * b0.y;
        }
    }
#pragma unroll
    for (int u = 0; u < U; u++) {
        ushort hs[4];
#pragma unroll
        for (int q = 0; q < 4; q++)
            hs[q] = __half_as_ushort(__float2half_rn(acc[u][q]));
        uint2 ph = make_uint2((uint32_t)hs[0] | ((uint32_t)hs[1] << 16),
                              (uint32_t)hs[2] | ((uint32_t)hs[3] << 16));
        ((uint2*)(outHi + (size_t)node * H))[lane + 32 * u] = ph;
    }
}

// ================= fp32 -> fp16 weight conversion (transposed, offset) =======
__global__ void wconv_kernel(const float* __restrict__ W, int K, int N, int off) {
    int idx = blockIdx.x * blockDim.x + threadIdx.x;
    if (idx >= N * K) return;
    int n = idx / K, k = idx - n * K;
    g_Whi[off + idx] = __float2half_rn(W[(size_t)k * N + n]);
}

// ================= tensor-core GEMM (pure fp16, mma.sync) ====================
#define MMA_F16(ACC, AF, B0, B1)                                                 \
    asm volatile(                                                                \
        "mma.sync.aligned.m16n8k16.row.col.f32.f16.f16.f32 "                     \
        "{%0,%1,%2,%3}, {%4,%5,%6,%7}, {%8,%9}, {%0,%1,%2,%3};"                  \
        : "+f"((ACC)[0]), "+f"((ACC)[1]), "+f"((ACC)[2]), "+f"((ACC)[3])         \
        : "r"((AF)[0]), "r"((AF)[1]), "r"((AF)[2]), "r"((AF)[3]),                \
          "r"(B0), "r"(B1))

// OUTMODE 0: fp16 out. OUTMODE 1: fused 512->4 dot + DIRECT graph pooling.
template <int BN, int OUTMODE>
__global__ __launch_bounds__(256) void gemm_mma(
    const __half* __restrict__ A, const __half* __restrict__ W,
    const float* __restrict__ bias, int M, int K, int N, int relu,
    __half* __restrict__ outH,
    const float* __restrict__ lw3, float* __restrict__ gsum,
    const int* __restrict__ batch) {
    constexpr int NA = BN / 32;
    constexpr int STAGE_A = 128 * 64;
    constexpr int STAGE_B = BN * 64;
    constexpr int STAGE = STAGE_A + STAGE_B;

    extern __shared__ char dynsm[];
    const uint32_t base0 = (smem_u32(dynsm) + 1023u) & ~1023u;

    const int tid = threadIdx.x;
    const int lane = tid & 31, wid = tid >> 5;
    const int wm = wid & 1, wn = wid >> 1;
    const int m0 = blockIdx.y * 128, n0 = blockIdx.x * BN;
    const int nch = K >> 5;

    float acc[4][NA][4];
#pragma unroll
    for (int i = 0; i < 4; i++)
#pragma unroll
        for (int j = 0; j < NA; j++)
#pragma unroll
            for (int q = 0; q < 4; q++) acc[i][j][q] = 0.f;

    auto fill = [&](int ci, int buf) {
        const int kb = ci * 64;
        const uint32_t st = base0 + buf * STAGE;
#pragma unroll
        for (int i = 0; i < 2; i++) {
            int t2 = tid + i * 256;
            int r = t2 >> 2, c = t2 & 3;
            int row = m0 + r;
            int rowc = (row < M) ? row : (M - 1);
            const char* src = (const char*)(A + (size_t)rowc * K) + kb + c * 16;
            uint32_t ssize = (row < M) ? 16u : 0u;
            uint32_t dst = st + (uint32_t)(r * 64 + ((c ^ ((r >> 1) & 3)) * 16));
            asm volatile("cp.async.cg.shared.global [%0], [%1], 16, %2;"
                         :: "r"(dst), "l"(src), "r"(ssize) : "memory");
        }
#pragma unroll
        for (int i = 0; i < BN / 64; i++) {
            int t2 = tid + i * 256;
            int r = t2 >> 2, c = t2 & 3;
            const char* src = (const char*)(W + (size_t)(n0 + r) * K) + kb + c * 16;
            uint32_t dst = st + STAGE_A + (uint32_t)(r * 64 + ((c ^ ((r >> 1) & 3)) * 16));
            asm volatile("cp.async.cg.shared.global [%0], [%1], 16;"
                         :: "r"(dst), "l"(src) : "memory");
        }
        asm volatile("cp.async.commit_group;" ::: "memory");
    };

    auto compute = [&](int buf) {
        const uint32_t st = base0 + buf * STAGE;
        const uint32_t aB = st, bB = st + STAGE_A;
#pragma unroll
        for (int ks = 0; ks < 2; ks++) {
            uint32_t ah[4][4];
#pragma unroll
            for (int ma = 0; ma < 4; ma++) {
                int r = wm * 64 + ma * 16 + (lane & 15);
                int c = ks * 2 + (lane >> 4);
                uint32_t off = (uint32_t)(r * 64 + ((c ^ ((r >> 1) & 3)) * 16));
                asm volatile("ldmatrix.sync.aligned.m8n8.x4.shared.b16 {%0,%1,%2,%3}, [%4];"
                             : "=r"(ah[ma][0]), "=r"(ah[ma][1]), "=r"(ah[ma][2]), "=r"(ah[ma][3])
                             : "r"(aB + off));
            }
#pragma unroll
            for (int nb = 0; nb < NA / 2; nb++) {
                int r = wn * (BN / 4) + nb * 16 + (lane & 7) + ((lane >> 4) & 1) * 8;
                int c = ks * 2 + ((lane >> 3) & 1);
                uint32_t off = (uint32_t)(r * 64 + ((c ^ ((r >> 1) & 3)) * 16));
                uint32_t b0, b1, b2, b3;
                asm volatile("ldmatrix.sync.aligned.m8n8.x4.shared.b16 {%0,%1,%2,%3}, [%4];"
                             : "=r"(b0), "=r"(b1), "=r"(b2), "=r"(b3) : "r"(bB + off));
#pragma unroll
                for (int ma = 0; ma < 4; ma++) {
                    MMA_F16(acc[ma][nb * 2], ah[ma], b0, b1);
                    MMA_F16(acc[ma][nb * 2 + 1], ah[ma], b2, b3);
                }
            }
        }
    };

    fill(0, 0);
    fill(1, 1);
    for (int ci = 0; ci < nch; ci++) {
        if (ci + 1 < nch) {
            asm volatile("cp.async.wait_group 1;" ::: "memory");
        } else {
            asm volatile("cp.async.wait_group 0;" ::: "memory");
        }
        __syncthreads();
        if (ci + 2 < nch) fill(ci + 2, (ci + 2) % 3);
        compute(ci % 3);
    }

    // ---- epilogue ----
#pragma unroll
    for (int ma = 0; ma < 4; ma++) {
        int r0 = m0 + wm * 64 + ma * 16 + (lane >> 2);
        float p0[4] = {0.f, 0.f, 0.f, 0.f}, p1[4] = {0.f, 0.f, 0.f, 0.f};
#pragma unroll
        for (int na = 0; na < NA; na++) {
            int c = n0 + wn * (BN / 4) + na * 8 + (lane & 3) * 2;
            float b0v = __ldg(bias + c), b1v = __ldg(bias + c + 1);
            float v00 = acc[ma][na][0] + b0v, v01 = acc[ma][na][1] + b1v;
            float v10 = acc[ma][na][2] + b0v, v11 = acc[ma][na][3] + b1v;
            if (relu) {
                v00 = fmaxf(v00, 0.f); v01 = fmaxf(v01, 0.f);
                v10 = fmaxf(v10, 0.f); v11 = fmaxf(v11, 0.f);
            }
            if (OUTMODE == 0) {
#pragma unroll
                for (int rr = 0; rr < 2; rr++) {
                    int row = r0 + rr * 8;
                    if (row >= M) continue;
                    float va = rr ? v10 : v00, vb = rr ? v11 : v01;
                    uint32_t hp = (uint32_t)__half_as_ushort(__float2half_rn(va)) |
                                  ((uint32_t)__half_as_ushort(__float2half_rn(vb)) << 16);
                    *(uint32_t*)(outH + (size_t)row * N + c) = hp;
                }
            } else {
                float4 w0 = __ldg((const float4*)(lw3 + c * 4));
                float4 w1 = __ldg((const float4*)(lw3 + (c + 1) * 4));
                p0[0] += v00 * w0.x + v01 * w1.x;  p0[1] += v00 * w0.y + v01 * w1.y;
                p0[2] += v00 * w0.z + v01 * w1.z;  p0[3] += v00 * w0.w + v01 * w1.w;
                p1[0] += v10 * w0.x + v11 * w1.x;  p1[1] += v10 * w0.y + v11 * w1.y;
                p1[2] += v10 * w0.z + v11 * w1.z;  p1[3] += v10 * w0.w + v11 * w1.w;
            }
        }
        if (OUTMODE == 1) {
#pragma unroll
            for (int j = 0; j < 4; j++) {
                p0[j] += __shfl_down_sync(0xffffffffu, p0[j], 2);
                p0[j] += __shfl_down_sync(0xffffffffu, p0[j], 1);
                p1[j] += __shfl_down_sync(0xffffffffu, p1[j], 2);
                p1[j] += __shfl_down_sync(0xffffffffu, p1[j], 1);
            }
            if ((lane & 3) == 0) {
                if (r0 < M) {
                    int g = __ldg(batch + r0);
#pragma unroll
                    for (int j = 0; j < 4; j++) atomicAdd(&gsum[g * 4 + j], p0[j]);
                }
                if (r0 + 8 < M) {
                    int g = __ldg(batch + r0 + 8);
#pragma unroll
                    for (int j = 0; j < 4; j++) atomicAdd(&gsum[g * 4 + j], p1[j]);
                }
            }
        }
    }
}

__global__ void finalize_kernel(float* __restrict__ out, const float* __restrict__ lb3) {
    int i = blockIdx.x * blockDim.x + threadIdx.x;
    if (i < NG * 4) {
        int cnt = g_gcnt[i >> 2];
        out[i] = (cnt > 0) ? (g_gsum[i] / (float)cnt + lb3[i & 3]) : 0.f;
    }
}

// ================= launch =================
extern "C" void kernel_launch(void* const* d_in, const int* in_sizes, int n_in,
                              void* d_out, int out_size) {
    const float* x    = (const float*)d_in[0];
    const int*   ei   = (const int*)d_in[1];
    const int*   bat  = (const int*)d_in[2];
    const float* W1   = (const float*)d_in[3];
    const float* b1   = (const float*)d_in[4];
    const float* W2   = (const float*)d_in[5];
    const float* b2   = (const float*)d_in[6];
    const float* W3   = (const float*)d_in[7];
    const float* b3   = (const float*)d_in[8];
    const float* lw1  = (const float*)d_in[9];
    const float* lb1  = (const float*)d_in[10];
    const float* lw2  = (const float*)d_in[11];
    const float* lb2  = (const float*)d_in[12];
    const float* lw3  = (const float*)d_in[13];
    const float* lb3  = (const float*)d_in[14];
    float* out = (float*)d_out;

    const int* src = ei;
    const int* dst = ei + NE;

    float* gsum;
    cudaGetSymbolAddress((void**)&gsum, g_gsum);
    __half *Ahi, *act1, *act2, *Whi;
    cudaGetSymbolAddress((void**)&Ahi, g_Ahi);
    cudaGetSymbolAddress((void**)&act1, g_act1);
    cudaGetSymbolAddress((void**)&act2, g_act2);
    cudaGetSymbolAddress((void**)&Whi, g_Whi);

    constexpr int SM_128 = 3 * (8192 + 128 * 64) + 1024;   // 50176
    constexpr int SM_256 = 3 * (8192 + 256 * 64) + 1024;   // 74752
    cudaFuncSetAttribute(gemm_mma<128, 0>, cudaFuncAttributeMaxDynamicSharedMemorySize, SM_128);
    cudaFuncSetAttribute(gemm_mma<256, 0>, cudaFuncAttributeMaxDynamicSharedMemorySize, SM_256);
    cudaFuncSetAttribute(gemm_mma<256, 1>, cudaFuncAttributeMaxDynamicSharedMemorySize, SM_256);

    // ---- side stream for conversions (fork-join inside graph capture) ----
    static cudaStream_t s2 = nullptr;
    static cudaEvent_t evFork = nullptr, evJoin = nullptr;
    if (s2 == nullptr) {
        cudaStreamCreateWithFlags(&s2, cudaStreamNonBlocking);
        cudaEventCreateWithFlags(&evFork, cudaEventDisableTiming);
        cudaEventCreateWithFlags(&evJoin, cudaEventDisableTiming);
    }

    // fork: conversions on s2 concurrent with graph preprocessing
    cudaEventRecord(evFork, 0);
    cudaStreamWaitEvent(s2, evFork, 0);

    wconv_kernel<<<(128 * 128 + 255) / 256, 256, 0, s2>>>(W1, 128, 128, OFF_W1);
    wconv_kernel<<<(256 * 128 + 255) / 256, 256, 0, s2>>>(W2, 128, 256, OFF_W2);
    wconv_kernel<<<(512 * 256 + 255) / 256, 256, 0, s2>>>(W3, 256, 512, OFF_W3);
    wconv_kernel<<<(1024 * 512 + 255) / 256, 256, 0, s2>>>(lw1, 512, 1024, OFF_L1);
    wconv_kernel<<<(512 * 1024 + 255) / 256, 256, 0, s2>>>(lw2, 1024, 512, OFF_L2);
    xconv_kernel<<<(int)(((size_t)NN * 128 + 255) / 256), 256, 0, s2>>>(x, act1, (size_t)NN * 128);
    cudaEventRecord(evJoin, s2);

    // ---- graph preprocessing (main stream, concurrent with s2) ----
    zero_kernel<<<(NN + 255) / 256, 256>>>();
    hist_kernel<<<(NE + 255) / 256, 256>>>(dst);
    scan1_kernel<<<NBLK, 256>>>();
    scan2_kernel<<<1, 512>>>();
    scan3_kernel<<<NBLK, 256>>>(bat);
    csr_fill_kernel<<<(NE + 255) / 256, 256>>>(src, dst);
    cudaStreamWaitEvent(0, evJoin, 0);

    const int aggBlocks = (NN + 3) / 4;
    const int tilesM = (NN + 127) / 128;   // 782

    // ---- layer 1 (K=128, N=128): act1 -> agg -> act2 ----
    agg16_kernel<128><<<aggBlocks, 128>>>(act1, Ahi);
    gemm_mma<128, 0><<<dim3(1, tilesM), 256, SM_128>>>(
        Ahi, Whi + OFF_W1, b1, NN, 128, 128, 1, act2, nullptr, nullptr, nullptr);

    // ---- layer 2 (K=128, N=256): act2 -> agg -> act1 ----
    agg16_kernel<128><<<aggBlocks, 128>>>(act2, Ahi);
    gemm_mma<256, 0><<<dim3(1, tilesM), 256, SM_256>>>(
        Ahi, Whi + OFF_W2, b2, NN, 128, 256, 1, act1, nullptr, nullptr, nullptr);

    // ---- layer 3 (K=256, N=512): act1 -> agg -> act2 ----
    agg16_kernel<256><<<aggBlocks, 128>>>(act1, Ahi);
    gemm_mma<256, 0><<<dim3(2, tilesM), 256, SM_256>>>(
        Ahi, Whi + OFF_W3, b3, NN, 256, 512, 0, act2, nullptr, nullptr, nullptr);

    // ---- MLP1 (K=512, N=1024): act2 -> act1 ----
    gemm_mma<256, 0><<<dim3(4, tilesM), 256, SM_256>>>(
        act2, Whi + OFF_L1, lb1, NN, 512, 1024, 1, act1, nullptr, nullptr, nullptr);

    // ---- MLP2 (K=1024, N=512): fused 512->4 dot + direct graph pooling ----
    gemm_mma<256, 1><<<dim3(2, tilesM), 256, SM_256>>>(
        act1, Whi + OFF_L2, lb2, NN, 1024, 512, 1, nullptr, lw3, gsum, bat);

    finalize_kernel<<<(NG * 4 + 255) / 256, 256>>>(out, lb3);
}

// round 16
// speedup vs baseline: 2.3423x; 2.3423x over previous
#include <cuda_runtime.h>
#include <cuda_fp16.h>
#include <cstdint>

#define NN 100000
#define NE 3200000
#define NG 256
#define NBLK 391   // ceil(NN/256)

// ---- weight plane offsets (elements) ----
#define OFF_W1  0          // 128x128  = 16384
#define OFF_W2  16384      // 256x128  = 32768
#define OFF_W3  49152      // 512x256  = 131072
#define OFF_L1  180224     // 1024x512 = 524288
#define OFF_L2  704512     // 512x1024 = 524288  -> end 1228800

// ================= device scratch (no allocations allowed) =================
__device__ int   g_cnt[NN];
__device__ int   g_rowptr[NN + 1];
__device__ int   g_cursor[NN];
__device__ int   g_bsum[NBLK];
__device__ int2  g_edge[NE];                  // (src, wgt bits) packed
__device__ float g_is[NN];
__device__ __half g_Ahi[(size_t)NN * 256];
__device__ __half g_act1[(size_t)NN * 1024];
__device__ __half g_act2[(size_t)NN * 1024];
__device__ __half g_Whi[1 << 21];
__device__ float g_nsum[(size_t)NN * 4];
__device__ float g_gsum[NG * 4];
__device__ int   g_gcnt[NG];

__device__ __forceinline__ uint32_t smem_u32(const void* p) {
    uint32_t a;
    asm("{ .reg .u64 t; cvta.to.shared.u64 t, %1; cvt.u32.u64 %0, t; }" : "=r"(a) : "l"(p));
    return a;
}

// ================= graph preprocessing =================
__global__ void zero_kernel() {
    int i = blockIdx.x * blockDim.x + threadIdx.x;
    if (i < NN) g_cnt[i] = 0;
    if (i < NN * 4) g_nsum[i] = 0.f;
    if (i < NG * 4) g_gsum[i] = 0.f;
    if (i < NG) g_gcnt[i] = 0;
}

__global__ void hist_kernel(const int* __restrict__ dst) {
    int e = blockIdx.x * blockDim.x + threadIdx.x;
    if (e < NE) atomicAdd(&g_cnt[dst[e]], 1);
}

__global__ void scan1_kernel() {
    int i = blockIdx.x * 256 + threadIdx.x;
    int v = (i < NN) ? g_cnt[i] : 0;
#pragma unroll
    for (int o = 16; o > 0; o >>= 1) v += __shfl_down_sync(0xffffffffu, v, o);
    __shared__ int ws[8];
    if ((threadIdx.x & 31) == 0) ws[threadIdx.x >> 5] = v;
    __syncthreads();
    if (threadIdx.x < 8) {
        int s = ws[threadIdx.x];
#pragma unroll
        for (int o = 4; o > 0; o >>= 1) s += __shfl_down_sync(0xffu, s, o);
        if (threadIdx.x == 0) g_bsum[blockIdx.x] = s;
    }
}

__global__ void scan2_kernel() {
    int tid = threadIdx.x;
    int v = (tid < NBLK) ? g_bsum[tid] : 0;
    __shared__ int sm[512];
    sm[tid] = v;
    __syncthreads();
    for (int o = 1; o < 512; o <<= 1) {
        int a = (tid >= o) ? sm[tid - o] : 0;
        __syncthreads();
        sm[tid] += a;
        __syncthreads();
    }
    if (tid < NBLK) g_bsum[tid] = sm[tid] - v;
    if (tid == NBLK - 1) g_rowptr[NN] = sm[tid];
}

// scan3 also folds invsqrt (saves a separate launch)
__global__ void scan3_kernel() {
    int i = blockIdx.x * 256 + threadIdx.x;
    int v = (i < NN) ? g_cnt[i] : 0;
    int lane = threadIdx.x & 31, w = threadIdx.x >> 5;
    int x = v;
#pragma unroll
    for (int o = 1; o < 32; o <<= 1) {
        int t = __shfl_up_sync(0xffffffffu, x, o);
        if (lane >= o) x += t;
    }
    __shared__ int ws[8];
    if (lane == 31) ws[w] = x;
    __syncthreads();
    if (threadIdx.x < 8) {
        int s = ws[threadIdx.x];
#pragma unroll
        for (int o = 1; o < 8; o <<= 1) {
            int t = __shfl_up_sync(0xffu, s, o);
            if ((int)threadIdx.x >= o) s += t;
        }
        ws[threadIdx.x] = s;
    }
    __syncthreads();
    int excl = x - v + (w ? ws[w - 1] : 0) + g_bsum[blockIdx.x];
    if (i < NN) {
        g_rowptr[i] = excl;
        g_cursor[i] = excl;
        g_is[i] = rsqrtf((float)(v + 1));
    }
}

__global__ void csr_fill_kernel(const int* __restrict__ src, const int* __restrict__ dst) {
    int e = blockIdx.x * blockDim.x + threadIdx.x;
    if (e >= NE) return;
    int d = dst[e];
    int s = src[e];
    int p = atomicAdd(&g_cursor[d], 1);
    g_edge[p] = make_int2(s, __float_as_int(g_is[s] * g_is[d]));
}

// ================= fp32 x -> fp16 plane =================
__global__ void xconv_kernel(const float* __restrict__ x, __half* __restrict__ o, size_t total) {
    size_t i = blockIdx.x * (size_t)blockDim.x + threadIdx.x;
    if (i < total) o[i] = __float2half_rn(x[i]);
}

// ================= aggregation: fp16 gather, fp32 accum, fp16 out ============
template <int H>
__global__ void agg16_kernel(const __half* __restrict__ h, __half* __restrict__ outHi) {
    const int node = blockIdx.x * 4 + (threadIdx.x >> 5);
    if (node >= NN) return;
    const int lane = threadIdx.x & 31;
    constexpr int U = H / 128;

    float acc[U][4];
    float self = g_is[node];
    self = self * self;
    const uint2* hrow = (const uint2*)(h + (size_t)node * H);
#pragma unroll
    for (int u = 0; u < U; u++) {
        uint2 t = hrow[lane + 32 * u];
        float2 a = __half22float2(*(const __half2*)&t.x);
        float2 b = __half22float2(*(const __half2*)&t.y);
        acc[u][0] = self * a.x; acc[u][1] = self * a.y;
        acc[u][2] = self * b.x; acc[u][3] = self * b.y;
    }
    const int beg = g_rowptr[node];
    const int end = g_rowptr[node + 1];
    int p = beg;
    for (; p + 2 <= end; p += 2) {
        int2 e0 = g_edge[p], e1 = g_edge[p + 1];
        float w0 = __int_as_float(e0.y), w1 = __int_as_float(e1.y);
        const uint2* s0 = (const uint2*)(h + (size_t)e0.x * H);
        const uint2* s1 = (const uint2*)(h + (size_t)e1.x * H);
#pragma unroll
        for (int u = 0; u < U; u++) {
            uint2 t0 = s0[lane + 32 * u];
            uint2 t1 = s1[lane + 32 * u];
            float2 a0 = __half22float2(*(const __half2*)&t0.x);
            float2 b0 = __half22float2(*(const __half2*)&t0.y);
            float2 a1 = __half22float2(*(const __half2*)&t1.x);
            float2 b1 = __half22float2(*(const __half2*)&t1.y);
            acc[u][0] += w0 * a0.x + w1 * a1.x;
            acc[u][1] += w0 * a0.y + w1 * a1.y;
            acc[u][2] += w0 * b0.x + w1 * b1.x;
            acc[u][3] += w0 * b0.y + w1 * b1.y;
        }
    }
    if (p < end) {
        int2 e0 = g_edge[p];
        float w0 = __int_as_float(e0.y);
        const uint2* s0 = (const uint2*)(h + (size_t)e0.x * H);
#pragma unroll
        for (int u = 0; u < U; u++) {
            uint2 t0 = s0[lane + 32 * u];
            float2 a0 = __half22float2(*(const __half2*)&t0.x);
            float2 b0 = __half22float2(*(const __half2*)&t0.y);
            acc[u][0] += w0 * a0.x; acc[u][1] += w0 * a0.y;
            acc[u][2] += w0 * b0.x; acc[u][3] += w0 * b0.y;
        }
    }
#pragma unroll
    for (int u = 0; u < U; u++) {
        ushort hs[4];
#pragma unroll
        for (int q = 0; q < 4; q++)
            hs[q] = __half_as_ushort(__float2half_rn(acc[u][q]));
        uint2 ph = make_uint2((uint32_t)hs[0] | ((uint32_t)hs[1] << 16),
                              (uint32_t)hs[2] | ((uint32_t)hs[3] << 16));
        ((uint2*)(outHi + (size_t)node * H))[lane + 32 * u] = ph;
    }
}

// ================= fp32 -> fp16 weight conversion (transposed, offset) =======
__global__ void wconv_kernel(const float* __restrict__ W, int K, int N, int off) {
    int idx = blockIdx.x * blockDim.x + threadIdx.x;
    if (idx >= N * K) return;
    int n = idx / K, k = idx - n * K;
    g_Whi[off + idx] = __float2half_rn(W[(size_t)k * N + n]);
}

// ================= tensor-core GEMM (pure fp16, mma.sync) ====================
#define MMA_F16(ACC, AF, B0, B1)                                                 \
    asm volatile(                                                                \
        "mma.sync.aligned.m16n8k16.row.col.f32.f16.f16.f32 "                     \
        "{%0,%1,%2,%3}, {%4,%5,%6,%7}, {%8,%9}, {%0,%1,%2,%3};"                  \
        : "+f"((ACC)[0]), "+f"((ACC)[1]), "+f"((ACC)[2]), "+f"((ACC)[3])         \
        : "r"((AF)[0]), "r"((AF)[1]), "r"((AF)[2]), "r"((AF)[3]),                \
          "r"(B0), "r"(B1))

// OUTMODE 0: fp16 out. OUTMODE 1: fused 512->4 dot + node-sum (uncontended).
template <int BN, int OUTMODE>
__global__ __launch_bounds__(256) void gemm_mma(
    const __half* __restrict__ A, const __half* __restrict__ W,
    const float* __restrict__ bias, int M, int K, int N, int relu,
    __half* __restrict__ outH,
    const float* __restrict__ lw3, float* __restrict__ nsum) {
    constexpr int NA = BN / 32;
    constexpr int STAGE_A = 128 * 64;
    constexpr int STAGE_B = BN * 64;
    constexpr int STAGE = STAGE_A + STAGE_B;

    extern __shared__ char dynsm[];
    const uint32_t base0 = (smem_u32(dynsm) + 1023u) & ~1023u;

    const int tid = threadIdx.x;
    const int lane = tid & 31, wid = tid >> 5;
    const int wm = wid & 1, wn = wid >> 1;
    const int m0 = blockIdx.y * 128, n0 = blockIdx.x * BN;
    const int nch = K >> 5;

    float acc[4][NA][4];
#pragma unroll
    for (int i = 0; i < 4; i++)
#pragma unroll
        for (int j = 0; j < NA; j++)
#pragma unroll
            for (int q = 0; q < 4; q++) acc[i][j][q] = 0.f;

    auto fill = [&](int ci, int buf) {
        const int kb = ci * 64;
        const uint32_t st = base0 + buf * STAGE;
#pragma unroll
        for (int i = 0; i < 2; i++) {
            int t2 = tid + i * 256;
            int r = t2 >> 2, c = t2 & 3;
            int row = m0 + r;
            int rowc = (row < M) ? row : (M - 1);
            const char* src = (const char*)(A + (size_t)rowc * K) + kb + c * 16;
            uint32_t ssize = (row < M) ? 16u : 0u;
            uint32_t dst = st + (uint32_t)(r * 64 + ((c ^ ((r >> 1) & 3)) * 16));
            asm volatile("cp.async.cg.shared.global [%0], [%1], 16, %2;"
                         :: "r"(dst), "l"(src), "r"(ssize) : "memory");
        }
#pragma unroll
        for (int i = 0; i < BN / 64; i++) {
            int t2 = tid + i * 256;
            int r = t2 >> 2, c = t2 & 3;
            const char* src = (const char*)(W + (size_t)(n0 + r) * K) + kb + c * 16;
            uint32_t dst = st + STAGE_A + (uint32_t)(r * 64 + ((c ^ ((r >> 1) & 3)) * 16));
            asm volatile("cp.async.cg.shared.global [%0], [%1], 16;"
                         :: "r"(dst), "l"(src) : "memory");
        }
        asm volatile("cp.async.commit_group;" ::: "memory");
    };

    auto compute = [&](int buf) {
        const uint32_t st = base0 + buf * STAGE;
        const uint32_t aB = st, bB = st + STAGE_A;
#pragma unroll
        for (int ks = 0; ks < 2; ks++) {
            uint32_t ah[4][4];
#pragma unroll
            for (int ma = 0; ma < 4; ma++) {
                int r = wm * 64 + ma * 16 + (lane & 15);
                int c = ks * 2 + (lane >> 4);
                uint32_t off = (uint32_t)(r * 64 + ((c ^ ((r >> 1) & 3)) * 16));
                asm volatile("ldmatrix.sync.aligned.m8n8.x4.shared.b16 {%0,%1,%2,%3}, [%4];"
                             : "=r"(ah[ma][0]), "=r"(ah[ma][1]), "=r"(ah[ma][2]), "=r"(ah[ma][3])
                             : "r"(aB + off));
            }
#pragma unroll
            for (int nb = 0; nb < NA / 2; nb++) {
                int r = wn * (BN / 4) + nb * 16 + (lane & 7) + ((lane >> 4) & 1) * 8;
                int c = ks * 2 + ((lane >> 3) & 1);
                uint32_t off = (uint32_t)(r * 64 + ((c ^ ((r >> 1) & 3)) * 16));
                uint32_t b0, b1, b2, b3;
                asm volatile("ldmatrix.sync.aligned.m8n8.x4.shared.b16 {%0,%1,%2,%3}, [%4];"
                             : "=r"(b0), "=r"(b1), "=r"(b2), "=r"(b3) : "r"(bB + off));
#pragma unroll
                for (int ma = 0; ma < 4; ma++) {
                    MMA_F16(acc[ma][nb * 2], ah[ma], b0, b1);
                    MMA_F16(acc[ma][nb * 2 + 1], ah[ma], b2, b3);
                }
            }
        }
    };

    fill(0, 0);
    fill(1, 1);
    for (int ci = 0; ci < nch; ci++) {
        if (ci + 1 < nch) {
            asm volatile("cp.async.wait_group 1;" ::: "memory");
        } else {
            asm volatile("cp.async.wait_group 0;" ::: "memory");
        }
        __syncthreads();
        if (ci + 2 < nch) fill(ci + 2, (ci + 2) % 3);
        compute(ci % 3);
    }

    // ---- epilogue ----
#pragma unroll
    for (int ma = 0; ma < 4; ma++) {
        int r0 = m0 + wm * 64 + ma * 16 + (lane >> 2);
        float p0[4] = {0.f, 0.f, 0.f, 0.f}, p1[4] = {0.f, 0.f, 0.f, 0.f};
#pragma unroll
        for (int na = 0; na < NA; na++) {
            int c = n0 + wn * (BN / 4) + na * 8 + (lane & 3) * 2;
            float b0v = __ldg(bias + c), b1v = __ldg(bias + c + 1);
            float v00 = acc[ma][na][0] + b0v, v01 = acc[ma][na][1] + b1v;
            float v10 = acc[ma][na][2] + b0v, v11 = acc[ma][na][3] + b1v;
            if (relu) {
                v00 = fmaxf(v00, 0.f); v01 = fmaxf(v01, 0.f);
                v10 = fmaxf(v10, 0.f); v11 = fmaxf(v11, 0.f);
            }
            if (OUTMODE == 0) {
#pragma unroll
                for (int rr = 0; rr < 2; rr++) {
                    int row = r0 + rr * 8;
                    if (row >= M) continue;
                    float va = rr ? v10 : v00, vb = rr ? v11 : v01;
                    uint32_t hp = (uint32_t)__half_as_ushort(__float2half_rn(va)) |
                                  ((uint32_t)__half_as_ushort(__float2half_rn(vb)) << 16);
                    *(uint32_t*)(outH + (size_t)row * N + c) = hp;
                }
            } else {
                float4 w0 = __ldg((const float4*)(lw3 + c * 4));
                float4 w1 = __ldg((const float4*)(lw3 + (c + 1) * 4));
                p0[0] += v00 * w0.x + v01 * w1.x;  p0[1] += v00 * w0.y + v01 * w1.y;
                p0[2] += v00 * w0.z + v01 * w1.z;  p0[3] += v00 * w0.w + v01 * w1.w;
                p1[0] += v10 * w0.x + v11 * w1.x;  p1[1] += v10 * w0.y + v11 * w1.y;
                p1[2] += v10 * w0.z + v11 * w1.z;  p1[3] += v10 * w0.w + v11 * w1.w;
            }
        }
        if (OUTMODE == 1) {
#pragma unroll
            for (int j = 0; j < 4; j++) {
                p0[j] += __shfl_down_sync(0xffffffffu, p0[j], 2);
                p0[j] += __shfl_down_sync(0xffffffffu, p0[j], 1);
                p1[j] += __shfl_down_sync(0xffffffffu, p1[j], 2);
                p1[j] += __shfl_down_sync(0xffffffffu, p1[j], 1);
            }
            if ((lane & 3) == 0) {
                if (r0 < M) {
#pragma unroll
                    for (int j = 0; j < 4; j++) atomicAdd(&nsum[(size_t)r0 * 4 + j], p0[j]);
                }
                if (r0 + 8 < M) {
#pragma unroll
                    for (int j = 0; j < 4; j++) atomicAdd(&nsum[(size_t)(r0 + 8) * 4 + j], p1[j]);
                }
            }
        }
    }
}

// ================= pooling (warp-aggregated, uncontended nsum read) ==========
__global__ void pool_kernel(const int* __restrict__ batch) {
    int i = blockIdx.x * 256 + threadIdx.x;
    int lane = threadIdx.x & 31;
    bool valid = i < NN;
    int g = valid ? batch[i] : -1;
    float4 v = valid ? *(const float4*)(g_nsum + (size_t)i * 4)
                     : make_float4(0.f, 0.f, 0.f, 0.f);
    int g0 = __shfl_sync(0xffffffffu, g, 0);
    bool uni = __all_sync(0xffffffffu, valid && g == g0);
    if (uni) {
#pragma unroll
        for (int o = 16; o > 0; o >>= 1) {
            v.x += __shfl_down_sync(0xffffffffu, v.x, o);
            v.y += __shfl_down_sync(0xffffffffu, v.y, o);
            v.z += __shfl_down_sync(0xffffffffu, v.z, o);
            v.w += __shfl_down_sync(0xffffffffu, v.w, o);
        }
        if (lane == 0) {
            atomicAdd(&g_gsum[g0 * 4 + 0], v.x);
            atomicAdd(&g_gsum[g0 * 4 + 1], v.y);
            atomicAdd(&g_gsum[g0 * 4 + 2], v.z);
            atomicAdd(&g_gsum[g0 * 4 + 3], v.w);
            atomicAdd(&g_gcnt[g0], 32);
        }
    } else if (valid) {
        atomicAdd(&g_gsum[g * 4 + 0], v.x);
        atomicAdd(&g_gsum[g * 4 + 1], v.y);
        atomicAdd(&g_gsum[g * 4 + 2], v.z);
        atomicAdd(&g_gsum[g * 4 + 3], v.w);
        atomicAdd(&g_gcnt[g], 1);
    }
}

__global__ void finalize_kernel(float* __restrict__ out, const float* __restrict__ lb3) {
    int i = blockIdx.x * blockDim.x + threadIdx.x;
    if (i < NG * 4) {
        int cnt = g_gcnt[i >> 2];
        out[i] = (cnt > 0) ? (g_gsum[i] / (float)cnt + lb3[i & 3]) : 0.f;
    }
}

// ================= launch =================
extern "C" void kernel_launch(void* const* d_in, const int* in_sizes, int n_in,
                              void* d_out, int out_size) {
    const float* x    = (const float*)d_in[0];
    const int*   ei   = (const int*)d_in[1];
    const int*   bat  = (const int*)d_in[2];
    const float* W1   = (const float*)d_in[3];
    const float* b1   = (const float*)d_in[4];
    const float* W2   = (const float*)d_in[5];
    const float* b2   = (const float*)d_in[6];
    const float* W3   = (const float*)d_in[7];
    const float* b3   = (const float*)d_in[8];
    const float* lw1  = (const float*)d_in[9];
    const float* lb1  = (const float*)d_in[10];
    const float* lw2  = (const float*)d_in[11];
    const float* lb2  = (const float*)d_in[12];
    const float* lw3  = (const float*)d_in[13];
    const float* lb3  = (const float*)d_in[14];
    float* out = (float*)d_out;

    const int* src = ei;
    const int* dst = ei + NE;

    float* nsum;
    cudaGetSymbolAddress((void**)&nsum, g_nsum);
    __half *Ahi, *act1, *act2, *Whi;
    cudaGetSymbolAddress((void**)&Ahi, g_Ahi);
    cudaGetSymbolAddress((void**)&act1, g_act1);
    cudaGetSymbolAddress((void**)&act2, g_act2);
    cudaGetSymbolAddress((void**)&Whi, g_Whi);

    constexpr int SM_128 = 3 * (8192 + 128 * 64) + 1024;   // 50176
    constexpr int SM_256 = 3 * (8192 + 256 * 64) + 1024;   // 74752
    cudaFuncSetAttribute(gemm_mma<128, 0>, cudaFuncAttributeMaxDynamicSharedMemorySize, SM_128);
    cudaFuncSetAttribute(gemm_mma<256, 0>, cudaFuncAttributeMaxDynamicSharedMemorySize, SM_256);
    cudaFuncSetAttribute(gemm_mma<256, 1>, cudaFuncAttributeMaxDynamicSharedMemorySize, SM_256);

    // ---- side stream for conversions (fork-join inside graph capture) ----
    static cudaStream_t s2 = nullptr;
    static cudaEvent_t evFork = nullptr, evJoin = nullptr;
    if (s2 == nullptr) {
        cudaStreamCreateWithFlags(&s2, cudaStreamNonBlocking);
        cudaEventCreateWithFlags(&evFork, cudaEventDisableTiming);
        cudaEventCreateWithFlags(&evJoin, cudaEventDisableTiming);
    }

    // fork: conversions on s2 concurrent with graph preprocessing
    cudaEventRecord(evFork, 0);
    cudaStreamWaitEvent(s2, evFork, 0);

    wconv_kernel<<<(128 * 128 + 255) / 256, 256, 0, s2>>>(W1, 128, 128, OFF_W1);
    wconv_kernel<<<(256 * 128 + 255) / 256, 256, 0, s2>>>(W2, 128, 256, OFF_W2);
    wconv_kernel<<<(512 * 256 + 255) / 256, 256, 0, s2>>>(W3, 256, 512, OFF_W3);
    wconv_kernel<<<(1024 * 512 + 255) / 256, 256, 0, s2>>>(lw1, 512, 1024, OFF_L1);
    wconv_kernel<<<(512 * 1024 + 255) / 256, 256, 0, s2>>>(lw2, 1024, 512, OFF_L2);
    xconv_kernel<<<(int)(((size_t)NN * 128 + 255) / 256), 256, 0, s2>>>(x, act1, (size_t)NN * 128);
    cudaEventRecord(evJoin, s2);

    // ---- graph preprocessing (main stream, concurrent with s2) ----
    zero_kernel<<<(NN * 4 + 255) / 256, 256>>>();
    hist_kernel<<<(NE + 255) / 256, 256>>>(dst);
    scan1_kernel<<<NBLK, 256>>>();
    scan2_kernel<<<1, 512>>>();
    scan3_kernel<<<NBLK, 256>>>();
    csr_fill_kernel<<<(NE + 255) / 256, 256>>>(src, dst);
    cudaStreamWaitEvent(0, evJoin, 0);

    const int aggBlocks = (NN + 3) / 4;
    const int tilesM = (NN + 127) / 128;   // 782

    // ---- layer 1 (K=128, N=128): act1 -> agg -> act2 ----
    agg16_kernel<128><<<aggBlocks, 128>>>(act1, Ahi);
    gemm_mma<128, 0><<<dim3(1, tilesM), 256, SM_128>>>(
        Ahi, Whi + OFF_W1, b1, NN, 128, 128, 1, act2, nullptr, nullptr);

    // ---- layer 2 (K=128, N=256): act2 -> agg -> act1 ----
    agg16_kernel<128><<<aggBlocks, 128>>>(act2, Ahi);
    gemm_mma<256, 0><<<dim3(1, tilesM), 256, SM_256>>>(
        Ahi, Whi + OFF_W2, b2, NN, 128, 256, 1, act1, nullptr, nullptr);

    // ---- layer 3 (K=256, N=512): act1 -> agg -> act2 ----
    agg16_kernel<256><<<aggBlocks, 128>>>(act1, Ahi);
    gemm_mma<256, 0><<<dim3(2, tilesM), 256, SM_256>>>(
        Ahi, Whi + OFF_W3, b3, NN, 256, 512, 0, act2, nullptr, nullptr);

    // ---- MLP1 (K=512, N=1024): act2 -> act1 ----
    gemm_mma<256, 0><<<dim3(4, tilesM), 256, SM_256>>>(
        act2, Whi + OFF_L1, lb1, NN, 512, 1024, 1, act1, nullptr, nullptr);

    // ---- MLP2 (K=1024, N=512), fused 512->4 + node-sum ----
    gemm_mma<256, 1><<<dim3(2, tilesM), 256, SM_256>>>(
        act1, Whi + OFF_L2, lb2, NN, 1024, 512, 1, nullptr, lw3, nsum);

    // ---- pooling ----
    pool_kernel<<<NBLK, 256>>>(bat);
    finalize_kernel<<<(NG * 4 + 255) / 256, 256>>>(out, lb3);
}

// round 17
// speedup vs baseline: 2.6904x; 1.1486x over previous
#include <cuda_runtime.h>
#include <cuda_fp16.h>
#include <cstdint>

#define NN 100000
#define NE 3200000
#define NG 256
#define NBLK 391   // ceil(NN/256)

// ---- weight plane offsets (elements) ----
#define OFF_W1  0          // 128x128  = 16384
#define OFF_W2  16384      // 256x128  = 32768
#define OFF_WF  49152      // 1024x256 = 262144 (fused W3@lw1)
#define OFF_L2  311296     // 512x1024 = 524288 -> end 835584

// ================= device scratch (no allocations allowed) =================
__device__ int   g_cnt[NN];
__device__ int   g_rowptr[NN + 1];
__device__ int   g_cursor[NN];
__device__ int   g_bsum[NBLK];
__device__ int2  g_edge[NE];                  // (src, wgt bits) packed
__device__ float g_is[NN];
__device__ __half g_Ahi[(size_t)NN * 256];
__device__ __half g_act1[(size_t)NN * 1024];
__device__ __half g_act2[(size_t)NN * 1024];
__device__ __half g_Whi[1 << 21];
__device__ float g_bf[1024];                  // fused bias b3@lw1 + lb1
__device__ float g_nsum[(size_t)NN * 4];
__device__ float g_gsum[NG * 4];
__device__ int   g_gcnt[NG];

__device__ __forceinline__ uint32_t smem_u32(const void* p) {
    uint32_t a;
    asm("{ .reg .u64 t; cvta.to.shared.u64 t, %1; cvt.u32.u64 %0, t; }" : "=r"(a) : "l"(p));
    return a;
}

// ================= graph preprocessing =================
__global__ void zero_kernel() {
    int i = blockIdx.x * blockDim.x + threadIdx.x;
    if (i < NN) g_cnt[i] = 0;
    if (i < NN * 4) g_nsum[i] = 0.f;
    if (i < NG * 4) g_gsum[i] = 0.f;
    if (i < NG) g_gcnt[i] = 0;
}

__global__ void hist_kernel(const int* __restrict__ dst) {
    int e = blockIdx.x * blockDim.x + threadIdx.x;
    if (e < NE) atomicAdd(&g_cnt[dst[e]], 1);
}

__global__ void scan1_kernel() {
    int i = blockIdx.x * 256 + threadIdx.x;
    int v = (i < NN) ? g_cnt[i] : 0;
#pragma unroll
    for (int o = 16; o > 0; o >>= 1) v += __shfl_down_sync(0xffffffffu, v, o);
    __shared__ int ws[8];
    if ((threadIdx.x & 31) == 0) ws[threadIdx.x >> 5] = v;
    __syncthreads();
    if (threadIdx.x < 8) {
        int s = ws[threadIdx.x];
#pragma unroll
        for (int o = 4; o > 0; o >>= 1) s += __shfl_down_sync(0xffu, s, o);
        if (threadIdx.x == 0) g_bsum[blockIdx.x] = s;
    }
}

__global__ void scan2_kernel() {
    int tid = threadIdx.x;
    int v = (tid < NBLK) ? g_bsum[tid] : 0;
    __shared__ int sm[512];
    sm[tid] = v;
    __syncthreads();
    for (int o = 1; o < 512; o <<= 1) {
        int a = (tid >= o) ? sm[tid - o] : 0;
        __syncthreads();
        sm[tid] += a;
        __syncthreads();
    }
    if (tid < NBLK) g_bsum[tid] = sm[tid] - v;
    if (tid == NBLK - 1) g_rowptr[NN] = sm[tid];
}

// scan3 also folds invsqrt
__global__ void scan3_kernel() {
    int i = blockIdx.x * 256 + threadIdx.x;
    int v = (i < NN) ? g_cnt[i] : 0;
    int lane = threadIdx.x & 31, w = threadIdx.x >> 5;
    int x = v;
#pragma unroll
    for (int o = 1; o < 32; o <<= 1) {
        int t = __shfl_up_sync(0xffffffffu, x, o);
        if (lane >= o) x += t;
    }
    __shared__ int ws[8];
    if (lane == 31) ws[w] = x;
    __syncthreads();
    if (threadIdx.x < 8) {
        int s = ws[threadIdx.x];
#pragma unroll
        for (int o = 1; o < 8; o <<= 1) {
            int t = __shfl_up_sync(0xffu, s, o);
            if ((int)threadIdx.x >= o) s += t;
        }
        ws[threadIdx.x] = s;
    }
    __syncthreads();
    int excl = x - v + (w ? ws[w - 1] : 0) + g_bsum[blockIdx.x];
    if (i < NN) {
        g_rowptr[i] = excl;
        g_cursor[i] = excl;
        g_is[i] = rsqrtf((float)(v + 1));
    }
}

__global__ void csr_fill_kernel(const int* __restrict__ src, const int* __restrict__ dst) {
    int e = blockIdx.x * blockDim.x + threadIdx.x;
    if (e >= NE) return;
    int d = dst[e];
    int s = src[e];
    int p = atomicAdd(&g_cursor[d], 1);
    g_edge[p] = make_int2(s, __float_as_int(g_is[s] * g_is[d]));
}

// ================= fp32 x -> fp16 plane =================
__global__ void xconv_kernel(const float* __restrict__ x, __half* __restrict__ o, size_t total) {
    size_t i = blockIdx.x * (size_t)blockDim.x + threadIdx.x;
    if (i < total) o[i] = __float2half_rn(x[i]);
}

// ================= aggregation: fp16 gather, fp32 accum, fp16 out ============
template <int H>
__global__ void agg16_kernel(const __half* __restrict__ h, __half* __restrict__ outHi) {
    const int node = blockIdx.x * 4 + (threadIdx.x >> 5);
    if (node >= NN) return;
    const int lane = threadIdx.x & 31;
    constexpr int U = H / 128;

    float acc[U][4];
    float self = g_is[node];
    self = self * self;
    const uint2* hrow = (const uint2*)(h + (size_t)node * H);
#pragma unroll
    for (int u = 0; u < U; u++) {
        uint2 t = hrow[lane + 32 * u];
        float2 a = __half22float2(*(const __half2*)&t.x);
        float2 b = __half22float2(*(const __half2*)&t.y);
        acc[u][0] = self * a.x; acc[u][1] = self * a.y;
        acc[u][2] = self * b.x; acc[u][3] = self * b.y;
    }
    const int beg = g_rowptr[node];
    const int end = g_rowptr[node + 1];
    int p = beg;
    for (; p + 2 <= end; p += 2) {
        int2 e0 = g_edge[p], e1 = g_edge[p + 1];
        float w0 = __int_as_float(e0.y), w1 = __int_as_float(e1.y);
        const uint2* s0 = (const uint2*)(h + (size_t)e0.x * H);
        const uint2* s1 = (const uint2*)(h + (size_t)e1.x * H);
#pragma unroll
        for (int u = 0; u < U; u++) {
            uint2 t0 = s0[lane + 32 * u];
            uint2 t1 = s1[lane + 32 * u];
            float2 a0 = __half22float2(*(const __half2*)&t0.x);
            float2 b0 = __half22float2(*(const __half2*)&t0.y);
            float2 a1 = __half22float2(*(const __half2*)&t1.x);
            float2 b1 = __half22float2(*(const __half2*)&t1.y);
            acc[u][0] += w0 * a0.x + w1 * a1.x;
            acc[u][1] += w0 * a0.y + w1 * a1.y;
            acc[u][2] += w0 * b0.x + w1 * b1.x;
            acc[u][3] += w0 * b0.y + w1 * b1.y;
        }
    }
    if (p < end) {
        int2 e0 = g_edge[p];
        float w0 = __int_as_float(e0.y);
        const uint2* s0 = (const uint2*)(h + (size_t)e0.x * H);
#pragma unroll
        for (int u = 0; u < U; u++) {
            uint2 t0 = s0[lane + 32 * u];
            float2 a0 = __half22float2(*(const __half2*)&t0.x);
            float2 b0 = __half22float2(*(const __half2*)&t0.y);
            acc[u][0] += w0 * a0.x; acc[u][1] += w0 * a0.y;
            acc[u][2] += w0 * b0.x; acc[u][3] += w0 * b0.y;
        }
    }
#pragma unroll
    for (int u = 0; u < U; u++) {
        ushort hs[4];
#pragma unroll
        for (int q = 0; q < 4; q++)
            hs[q] = __half_as_ushort(__float2half_rn(acc[u][q]));
        uint2 ph = make_uint2((uint32_t)hs[0] | ((uint32_t)hs[1] << 16),
                              (uint32_t)hs[2] | ((uint32_t)hs[3] << 16));
        ((uint2*)(outHi + (size_t)node * H))[lane + 32 * u] = ph;
    }
}

// ================= fp32 -> fp16 weight conversion (transposed, offset) =======
__global__ void wconv_kernel(const float* __restrict__ W, int K, int N, int off) {
    int idx = blockIdx.x * blockDim.x + threadIdx.x;
    if (idx >= N * K) return;
    int n = idx / K, k = idx - n * K;
    g_Whi[off + idx] = __float2half_rn(W[(size_t)k * N + n]);
}

// ================= fused weight Wf = W3 @ lw1 (fp32 compute, fp16 store) =====
// W3: [256, 512] row-major; lw1: [512, 1024] row-major.
// Output layout N-major: g_Whi[OFF_WF + n*256 + k].
// Block: 256 threads = one n-quarter; 4 k-rows per block.
__global__ void wf_kernel(const float* __restrict__ W3, const float* __restrict__ lw1) {
    int n = (blockIdx.x & 3) * 256 + threadIdx.x;
    int k0 = (blockIdx.x >> 2) * 4;
    float s0 = 0.f, s1 = 0.f, s2 = 0.f, s3 = 0.f;
    const float* w0 = W3 + (size_t)(k0 + 0) * 512;
    const float* w1 = W3 + (size_t)(k0 + 1) * 512;
    const float* w2 = W3 + (size_t)(k0 + 2) * 512;
    const float* w3 = W3 + (size_t)(k0 + 3) * 512;
    for (int j = 0; j < 512; j++) {
        float lv = __ldg(lw1 + (size_t)j * 1024 + n);
        s0 += __ldg(w0 + j) * lv;
        s1 += __ldg(w1 + j) * lv;
        s2 += __ldg(w2 + j) * lv;
        s3 += __ldg(w3 + j) * lv;
    }
    g_Whi[OFF_WF + (size_t)n * 256 + k0 + 0] = __float2half_rn(s0);
    g_Whi[OFF_WF + (size_t)n * 256 + k0 + 1] = __float2half_rn(s1);
    g_Whi[OFF_WF + (size_t)n * 256 + k0 + 2] = __float2half_rn(s2);
    g_Whi[OFF_WF + (size_t)n * 256 + k0 + 3] = __float2half_rn(s3);
}

// bf = b3 @ lw1 + lb1  (fp32)
__global__ void bf_kernel(const float* __restrict__ b3, const float* __restrict__ lw1,
                          const float* __restrict__ lb1) {
    int n = blockIdx.x * 256 + threadIdx.x;
    if (n >= 1024) return;
    float s = lb1[n];
    for (int j = 0; j < 512; j++) s += b3[j] * __ldg(lw1 + (size_t)j * 1024 + n);
    g_bf[n] = s;
}

// ================= tensor-core GEMM (pure fp16, mma.sync) ====================
#define MMA_F16(ACC, AF, B0, B1)                                                 \
    asm volatile(                                                                \
        "mma.sync.aligned.m16n8k16.row.col.f32.f16.f16.f32 "                     \
        "{%0,%1,%2,%3}, {%4,%5,%6,%7}, {%8,%9}, {%0,%1,%2,%3};"                  \
        : "+f"((ACC)[0]), "+f"((ACC)[1]), "+f"((ACC)[2]), "+f"((ACC)[3])         \
        : "r"((AF)[0]), "r"((AF)[1]), "r"((AF)[2]), "r"((AF)[3]),                \
          "r"(B0), "r"(B1))

// OUTMODE 0: fp16 out. OUTMODE 1: fused 512->4 dot + node-sum (uncontended).
template <int BN, int OUTMODE>
__global__ __launch_bounds__(256) void gemm_mma(
    const __half* __restrict__ A, const __half* __restrict__ W,
    const float* __restrict__ bias, int M, int K, int N, int relu,
    __half* __restrict__ outH,
    const float* __restrict__ lw3, float* __restrict__ nsum) {
    constexpr int NA = BN / 32;
    constexpr int STAGE_A = 128 * 64;
    constexpr int STAGE_B = BN * 64;
    constexpr int STAGE = STAGE_A + STAGE_B;

    extern __shared__ char dynsm[];
    const uint32_t base0 = (smem_u32(dynsm) + 1023u) & ~1023u;

    const int tid = threadIdx.x;
    const int lane = tid & 31, wid = tid >> 5;
    const int wm = wid & 1, wn = wid >> 1;
    const int m0 = blockIdx.y * 128, n0 = blockIdx.x * BN;
    const int nch = K >> 5;

    float acc[4][NA][4];
#pragma unroll
    for (int i = 0; i < 4; i++)
#pragma unroll
        for (int j = 0; j < NA; j++)
#pragma unroll
            for (int q = 0; q < 4; q++) acc[i][j][q] = 0.f;

    auto fill = [&](int ci, int buf) {
        const int kb = ci * 64;
        const uint32_t st = base0 + buf * STAGE;
#pragma unroll
        for (int i = 0; i < 2; i++) {
            int t2 = tid + i * 256;
            int r = t2 >> 2, c = t2 & 3;
            int row = m0 + r;
            int rowc = (row < M) ? row : (M - 1);
            const char* src = (const char*)(A + (size_t)rowc * K) + kb + c * 16;
            uint32_t ssize = (row < M) ? 16u : 0u;
            uint32_t dst = st + (uint32_t)(r * 64 + ((c ^ ((r >> 1) & 3)) * 16));
            asm volatile("cp.async.cg.shared.global [%0], [%1], 16, %2;"
                         :: "r"(dst), "l"(src), "r"(ssize) : "memory");
        }
#pragma unroll
        for (int i = 0; i < BN / 64; i++) {
            int t2 = tid + i * 256;
            int r = t2 >> 2, c = t2 & 3;
            const char* src = (const char*)(W + (size_t)(n0 + r) * K) + kb + c * 16;
            uint32_t dst = st + STAGE_A + (uint32_t)(r * 64 + ((c ^ ((r >> 1) & 3)) * 16));
            asm volatile("cp.async.cg.shared.global [%0], [%1], 16;"
                         :: "r"(dst), "l"(src) : "memory");
        }
        asm volatile("cp.async.commit_group;" ::: "memory");
    };

    auto compute = [&](int buf) {
        const uint32_t st = base0 + buf * STAGE;
        const uint32_t aB = st, bB = st + STAGE_A;
#pragma unroll
        for (int ks = 0; ks < 2; ks++) {
            uint32_t ah[4][4];
#pragma unroll
            for (int ma = 0; ma < 4; ma++) {
                int r = wm * 64 + ma * 16 + (lane & 15);
                int c = ks * 2 + (lane >> 4);
                uint32_t off = (uint32_t)(r * 64 + ((c ^ ((r >> 1) & 3)) * 16));
                asm volatile("ldmatrix.sync.aligned.m8n8.x4.shared.b16 {%0,%1,%2,%3}, [%4];"
                             : "=r"(ah[ma][0]), "=r"(ah[ma][1]), "=r"(ah[ma][2]), "=r"(ah[ma][3])
                             : "r"(aB + off));
            }
#pragma unroll
            for (int nb = 0; nb < NA / 2; nb++) {
                int r = wn * (BN / 4) + nb * 16 + (lane & 7) + ((lane >> 4) & 1) * 8;
                int c = ks * 2 + ((lane >> 3) & 1);
                uint32_t off = (uint32_t)(r * 64 + ((c ^ ((r >> 1) & 3)) * 16));
                uint32_t b0, b1, b2, b3;
                asm volatile("ldmatrix.sync.aligned.m8n8.x4.shared.b16 {%0,%1,%2,%3}, [%4];"
                             : "=r"(b0), "=r"(b1), "=r"(b2), "=r"(b3) : "r"(bB + off));
#pragma unroll
                for (int ma = 0; ma < 4; ma++) {
                    MMA_F16(acc[ma][nb * 2], ah[ma], b0, b1);
                    MMA_F16(acc[ma][nb * 2 + 1], ah[ma], b2, b3);
                }
            }
        }
    };

    fill(0, 0);
    fill(1, 1);
    for (int ci = 0; ci < nch; ci++) {
        if (ci + 1 < nch) {
            asm volatile("cp.async.wait_group 1;" ::: "memory");
        } else {
            asm volatile("cp.async.wait_group 0;" ::: "memory");
        }
        __syncthreads();
        if (ci + 2 < nch) fill(ci + 2, (ci + 2) % 3);
        compute(ci % 3);
    }

    // ---- epilogue ----
#pragma unroll
    for (int ma = 0; ma < 4; ma++) {
        int r0 = m0 + wm * 64 + ma * 16 + (lane >> 2);
        float p0[4] = {0.f, 0.f, 0.f, 0.f}, p1[4] = {0.f, 0.f, 0.f, 0.f};
#pragma unroll
        for (int na = 0; na < NA; na++) {
            int c = n0 + wn * (BN / 4) + na * 8 + (lane & 3) * 2;
            float b0v = __ldg(bias + c), b1v = __ldg(bias + c + 1);
            float v00 = acc[ma][na][0] + b0v, v01 = acc[ma][na][1] + b1v;
            float v10 = acc[ma][na][2] + b0v, v11 = acc[ma][na][3] + b1v;
            if (relu) {
                v00 = fmaxf(v00, 0.f); v01 = fmaxf(v01, 0.f);
                v10 = fmaxf(v10, 0.f); v11 = fmaxf(v11, 0.f);
            }
            if (OUTMODE == 0) {
#pragma unroll
                for (int rr = 0; rr < 2; rr++) {
                    int row = r0 + rr * 8;
                    if (row >= M) continue;
                    float va = rr ? v10 : v00, vb = rr ? v11 : v01;
                    uint32_t hp = (uint32_t)__half_as_ushort(__float2half_rn(va)) |
                                  ((uint32_t)__half_as_ushort(__float2half_rn(vb)) << 16);
                    *(uint32_t*)(outH + (size_t)row * N + c) = hp;
                }
            } else {
                float4 w0 = __ldg((const float4*)(lw3 + c * 4));
                float4 w1 = __ldg((const float4*)(lw3 + (c + 1) * 4));
                p0[0] += v00 * w0.x + v01 * w1.x;  p0[1] += v00 * w0.y + v01 * w1.y;
                p0[2] += v00 * w0.z + v01 * w1.z;  p0[3] += v00 * w0.w + v01 * w1.w;
                p1[0] += v10 * w0.x + v11 * w1.x;  p1[1] += v10 * w0.y + v11 * w1.y;
                p1[2] += v10 * w0.z + v11 * w1.z;  p1[3] += v10 * w0.w + v11 * w1.w;
            }
        }
        if (OUTMODE == 1) {
#pragma unroll
            for (int j = 0; j < 4; j++) {
                p0[j] += __shfl_down_sync(0xffffffffu, p0[j], 2);
                p0[j] += __shfl_down_sync(0xffffffffu, p0[j], 1);
                p1[j] += __shfl_down_sync(0xffffffffu, p1[j], 2);
                p1[j] += __shfl_down_sync(0xffffffffu, p1[j], 1);
            }
            if ((lane & 3) == 0) {
                if (r0 < M) {
#pragma unroll
                    for (int j = 0; j < 4; j++) atomicAdd(&nsum[(size_t)r0 * 4 + j], p0[j]);
                }
                if (r0 + 8 < M) {
#pragma unroll
                    for (int j = 0; j < 4; j++) atomicAdd(&nsum[(size_t)(r0 + 8) * 4 + j], p1[j]);
                }
            }
        }
    }
}

// ================= pooling (warp-aggregated, uncontended nsum read) ==========
__global__ void pool_kernel(const int* __restrict__ batch) {
    int i = blockIdx.x * 256 + threadIdx.x;
    int lane = threadIdx.x & 31;
    bool valid = i < NN;
    int g = valid ? batch[i] : -1;
    float4 v = valid ? *(const float4*)(g_nsum + (size_t)i * 4)
                     : make_float4(0.f, 0.f, 0.f, 0.f);
    int g0 = __shfl_sync(0xffffffffu, g, 0);
    bool uni = __all_sync(0xffffffffu, valid && g == g0);
    if (uni) {
#pragma unroll
        for (int o = 16; o > 0; o >>= 1) {
            v.x += __shfl_down_sync(0xffffffffu, v.x, o);
            v.y += __shfl_down_sync(0xffffffffu, v.y, o);
            v.z += __shfl_down_sync(0xffffffffu, v.z, o);
            v.w += __shfl_down_sync(0xffffffffu, v.w, o);
        }
        if (lane == 0) {
            atomicAdd(&g_gsum[g0 * 4 + 0], v.x);
            atomicAdd(&g_gsum[g0 * 4 + 1], v.y);
            atomicAdd(&g_gsum[g0 * 4 + 2], v.z);
            atomicAdd(&g_gsum[g0 * 4 + 3], v.w);
            atomicAdd(&g_gcnt[g0], 32);
        }
    } else if (valid) {
        atomicAdd(&g_gsum[g * 4 + 0], v.x);
        atomicAdd(&g_gsum[g * 4 + 1], v.y);
        atomicAdd(&g_gsum[g * 4 + 2], v.z);
        atomicAdd(&g_gsum[g * 4 + 3], v.w);
        atomicAdd(&g_gcnt[g], 1);
    }
}

__global__ void finalize_kernel(float* __restrict__ out, const float* __restrict__ lb3) {
    int i = blockIdx.x * blockDim.x + threadIdx.x;
    if (i < NG * 4) {
        int cnt = g_gcnt[i >> 2];
        out[i] = (cnt > 0) ? (g_gsum[i] / (float)cnt + lb3[i & 3]) : 0.f;
    }
}

// ================= launch =================
extern "C" void kernel_launch(void* const* d_in, const int* in_sizes, int n_in,
                              void* d_out, int out_size) {
    const float* x    = (const float*)d_in[0];
    const int*   ei   = (const int*)d_in[1];
    const int*   bat  = (const int*)d_in[2];
    const float* W1   = (const float*)d_in[3];
    const float* b1   = (const float*)d_in[4];
    const float* W2   = (const float*)d_in[5];
    const float* b2   = (const float*)d_in[6];
    const float* W3   = (const float*)d_in[7];
    const float* b3   = (const float*)d_in[8];
    const float* lw1  = (const float*)d_in[9];
    const float* lb1  = (const float*)d_in[10];
    const float* lw2  = (const float*)d_in[11];
    const float* lb2  = (const float*)d_in[12];
    const float* lw3  = (const float*)d_in[13];
    const float* lb3  = (const float*)d_in[14];
    float* out = (float*)d_out;

    const int* src = ei;
    const int* dst = ei + NE;

    float *nsum, *bf;
    cudaGetSymbolAddress((void**)&nsum, g_nsum);
    cudaGetSymbolAddress((void**)&bf, g_bf);
    __half *Ahi, *act1, *act2, *Whi;
    cudaGetSymbolAddress((void**)&Ahi, g_Ahi);
    cudaGetSymbolAddress((void**)&act1, g_act1);
    cudaGetSymbolAddress((void**)&act2, g_act2);
    cudaGetSymbolAddress((void**)&Whi, g_Whi);

    constexpr int SM_128 = 3 * (8192 + 128 * 64) + 1024;   // 50176
    constexpr int SM_256 = 3 * (8192 + 256 * 64) + 1024;   // 74752
    cudaFuncSetAttribute(gemm_mma<128, 0>, cudaFuncAttributeMaxDynamicSharedMemorySize, SM_128);
    cudaFuncSetAttribute(gemm_mma<256, 0>, cudaFuncAttributeMaxDynamicSharedMemorySize, SM_256);
    cudaFuncSetAttribute(gemm_mma<256, 1>, cudaFuncAttributeMaxDynamicSharedMemorySize, SM_256);

    // ---- side stream for conversions + fused-weight precompute ----
    static cudaStream_t s2 = nullptr;
    static cudaEvent_t evFork = nullptr, evJoin = nullptr;
    if (s2 == nullptr) {
        cudaStreamCreateWithFlags(&s2, cudaStreamNonBlocking);
        cudaEventCreateWithFlags(&evFork, cudaEventDisableTiming);
        cudaEventCreateWithFlags(&evJoin, cudaEventDisableTiming);
    }

    cudaEventRecord(evFork, 0);
    cudaStreamWaitEvent(s2, evFork, 0);

    wconv_kernel<<<(128 * 128 + 255) / 256, 256, 0, s2>>>(W1, 128, 128, OFF_W1);
    wconv_kernel<<<(256 * 128 + 255) / 256, 256, 0, s2>>>(W2, 128, 256, OFF_W2);
    wconv_kernel<<<(512 * 1024 + 255) / 256, 256, 0, s2>>>(lw2, 1024, 512, OFF_L2);
    wf_kernel<<<256, 256, 0, s2>>>(W3, lw1);         // Wf = W3 @ lw1 (fp32->fp16)
    bf_kernel<<<4, 256, 0, s2>>>(b3, lw1, lb1);      // bf = b3 @ lw1 + lb1
    xconv_kernel<<<(int)(((size_t)NN * 128 + 255) / 256), 256, 0, s2>>>(x, act1, (size_t)NN * 128);
    cudaEventRecord(evJoin, s2);

    // ---- graph preprocessing (main stream, concurrent with s2) ----
    zero_kernel<<<(NN * 4 + 255) / 256, 256>>>();
    hist_kernel<<<(NE + 255) / 256, 256>>>(dst);
    scan1_kernel<<<NBLK, 256>>>();
    scan2_kernel<<<1, 512>>>();
    scan3_kernel<<<NBLK, 256>>>();
    csr_fill_kernel<<<(NE + 255) / 256, 256>>>(src, dst);
    cudaStreamWaitEvent(0, evJoin, 0);

    const int aggBlocks = (NN + 3) / 4;
    const int tilesM = (NN + 127) / 128;   // 782

    // ---- layer 1 (K=128, N=128): act1 -> agg -> act2 ----
    agg16_kernel<128><<<aggBlocks, 128>>>(act1, Ahi);
    gemm_mma<128, 0><<<dim3(1, tilesM), 256, SM_128>>>(
        Ahi, Whi + OFF_W1, b1, NN, 128, 128, 1, act2, nullptr, nullptr);

    // ---- layer 2 (K=128, N=256): act2 -> agg -> act1 ----
    agg16_kernel<128><<<aggBlocks, 128>>>(act2, Ahi);
    gemm_mma<256, 0><<<dim3(1, tilesM), 256, SM_256>>>(
        Ahi, Whi + OFF_W2, b2, NN, 128, 256, 1, act1, nullptr, nullptr);

    // ---- fused L3+MLP1 (K=256, N=1024): act1 -> agg -> act2, relu ----
    agg16_kernel<256><<<aggBlocks, 128>>>(act1, Ahi);
    gemm_mma<256, 0><<<dim3(4, tilesM), 256, SM_256>>>(
        Ahi, Whi + OFF_WF, bf, NN, 256, 1024, 1, act2, nullptr, nullptr);

    // ---- MLP2 (K=1024, N=512), fused 512->4 + node-sum ----
    gemm_mma<256, 1><<<dim3(2, tilesM), 256, SM_256>>>(
        act2, Whi + OFF_L2, lb2, NN, 1024, 512, 1, nullptr, lw3, nsum);

    // ---- pooling ----
    pool_kernel<<<NBLK, 256>>>(bat);
    finalize_kernel<<<(NG * 4 + 255) / 256, 256>>>(out, lb3);
}